// round 1
// baseline (speedup 1.0000x reference)
#include <cuda_runtime.h>
#include <math.h>

#define BATCH 8
#define SEQ   512
#define CDIM  2048
#define NH    16
#define HD    128
#define MTOK  (BATCH*SEQ)      // 4096
#define F3    (3*CDIM)         // 6144

// Scratch (static device arrays; no allocation in kernel_launch)
__device__ float g_qkv[MTOK * F3];              // 100.7 MB
__device__ float g_q[BATCH*NH*SEQ*HD];          // 33.5 MB  [B,H,T,hd]
__device__ float g_k[BATCH*NH*SEQ*HD];
__device__ float g_v[BATCH*NH*SEQ*HD];
__device__ float g_y[MTOK * CDIM];              // 33.5 MB  [B,T,C]

// ---------------------------------------------------------------------------
// C[M,N] = A[M,K] * B[N,K]^T   (both row-major, K contiguous: "NT" gemm)
// 128x128 block tile, BK=8, 256 threads, 8x8 micro-tile per thread.
// M, N, K must be multiples of 128/128/8 (true for all uses here).
// ---------------------------------------------------------------------------
__global__ __launch_bounds__(256) void sgemm_nt(
    const float* __restrict__ A, const float* __restrict__ B,
    float* __restrict__ Cm, int Ndim, int Kdim)
{
    __shared__ float As[8][128];
    __shared__ float Bs[8][128];

    const int tid = threadIdx.x;
    const int m0 = blockIdx.y * 128;
    const int n0 = blockIdx.x * 128;

    const int lr = tid >> 1;          // 0..127 : tile row being loaded
    const int lc = (tid & 1) * 4;     // 0 or 4 : k offset (float4)

    const float* Ap = A + (size_t)(m0 + lr) * Kdim + lc;
    const float* Bp = B + (size_t)(n0 + lr) * Kdim + lc;

    const int ty = tid >> 4;          // 0..15
    const int tx = tid & 15;          // 0..15

    float acc[8][8];
#pragma unroll
    for (int i = 0; i < 8; i++)
#pragma unroll
        for (int j = 0; j < 8; j++) acc[i][j] = 0.0f;

    for (int k0 = 0; k0 < Kdim; k0 += 8) {
        float4 av = *(const float4*)(Ap + k0);
        float4 bv = *(const float4*)(Bp + k0);
        __syncthreads();
        As[lc + 0][lr] = av.x; As[lc + 1][lr] = av.y;
        As[lc + 2][lr] = av.z; As[lc + 3][lr] = av.w;
        Bs[lc + 0][lr] = bv.x; Bs[lc + 1][lr] = bv.y;
        Bs[lc + 2][lr] = bv.z; Bs[lc + 3][lr] = bv.w;
        __syncthreads();

#pragma unroll
        for (int kk = 0; kk < 8; kk++) {
            float a[8], b[8];
            *(float4*)(a)     = *(const float4*)(&As[kk][ty * 8]);
            *(float4*)(a + 4) = *(const float4*)(&As[kk][ty * 8 + 4]);
            *(float4*)(b)     = *(const float4*)(&Bs[kk][tx * 8]);
            *(float4*)(b + 4) = *(const float4*)(&Bs[kk][tx * 8 + 4]);
#pragma unroll
            for (int i = 0; i < 8; i++)
#pragma unroll
                for (int j = 0; j < 8; j++)
                    acc[i][j] = fmaf(a[i], b[j], acc[i][j]);
        }
    }

#pragma unroll
    for (int i = 0; i < 8; i++) {
        float* cp = Cm + (size_t)(m0 + ty * 8 + i) * Ndim + n0 + tx * 8;
        float4 v0 = make_float4(acc[i][0], acc[i][1], acc[i][2], acc[i][3]);
        float4 v1 = make_float4(acc[i][4], acc[i][5], acc[i][6], acc[i][7]);
        *(float4*)(cp)     = v0;
        *(float4*)(cp + 4) = v1;
    }
}

// ---------------------------------------------------------------------------
// RoPE (first 16 dims of q,k) + split qkv -> q,k,v in [B,H,T,hd] layout.
// grid: MTOK*NH blocks, 128 threads (one per head dim)
// ---------------------------------------------------------------------------
__global__ __launch_bounds__(128) void rope_split_kernel()
{
    int blk = blockIdx.x;                 // (b*SEQ + t)*NH + h
    int h  = blk % NH;
    int bt = blk / NH;                    // b*SEQ + t
    int t  = bt % SEQ;
    int b  = bt / SEQ;
    int d  = threadIdx.x;

    const float* src = g_qkv + (size_t)bt * F3 + h * HD;
    size_t dst = ((size_t)(b * NH + h) * SEQ + t) * HD + d;

    float qv = src[d];
    float kv = src[CDIM + d];
    float vv = src[2 * CDIM + d];

    if (d < 16) {
        int i = d & 7;
        float freq = powf(10000.0f, -(float)i * 0.125f);
        float ang = (float)t * freq;
        float s, c;
        sincosf(ang, &s, &c);
        if (d < 8) {
            float q2 = src[d + 8];
            float k2 = src[CDIM + d + 8];
            qv = qv * c - q2 * s;
            kv = kv * c - k2 * s;
        } else {
            float q1 = src[d - 8];
            float k1 = src[CDIM + d - 8];
            qv = qv * c + q1 * s;
            kv = kv * c + k1 * s;
        }
    }
    g_q[dst] = qv;
    g_k[dst] = kv;
    g_v[dst] = vv;
}

// ---------------------------------------------------------------------------
// Causal attention, online softmax. One warp per query row; 8 warps/block.
// K/V staged through shared memory in 32-key tiles.
// grid: (SEQ/8, BATCH*NH), 256 threads
// ---------------------------------------------------------------------------
#define KT 32
__global__ __launch_bounds__(256) void attn_kernel()
{
    __shared__ float Ks[KT][HD];
    __shared__ float Vs[KT][HD];

    const int bh   = blockIdx.y;            // b*NH + h
    const int qt   = blockIdx.x;
    const int warp = threadIdx.x >> 5;
    const int lane = threadIdx.x & 31;
    const int qi   = qt * 8 + warp;

    const float* qrow = g_q + ((size_t)bh * SEQ + qi) * HD;
    float qr[4];
#pragma unroll
    for (int j = 0; j < 4; j++)
        qr[j] = qrow[lane + 32 * j] * 0.08838834764831845f;   // 1/sqrt(128)

    float m = -1e30f, l = 0.0f;
    float acc[4] = {0.f, 0.f, 0.f, 0.f};

    const int kmax = qt * 8 + 7;            // largest key any warp needs
    for (int kt0 = 0; kt0 <= kmax; kt0 += KT) {
        __syncthreads();
        const float4* kb = (const float4*)(g_k + ((size_t)bh * SEQ + kt0) * HD);
        const float4* vb = (const float4*)(g_v + ((size_t)bh * SEQ + kt0) * HD);
        float4* ks4 = (float4*)Ks;
        float4* vs4 = (float4*)Vs;
#pragma unroll
        for (int i = threadIdx.x; i < KT * HD / 4; i += 256) {
            ks4[i] = kb[i];
            vs4[i] = vb[i];
        }
        __syncthreads();

        int kend = qi - kt0 + 1;
        if (kend > KT) kend = KT;
        for (int kk = 0; kk < kend; kk++) {
            float s = qr[0] * Ks[kk][lane]      + qr[1] * Ks[kk][lane + 32]
                    + qr[2] * Ks[kk][lane + 64] + qr[3] * Ks[kk][lane + 96];
            s += __shfl_xor_sync(0xffffffffu, s, 16);
            s += __shfl_xor_sync(0xffffffffu, s, 8);
            s += __shfl_xor_sync(0xffffffffu, s, 4);
            s += __shfl_xor_sync(0xffffffffu, s, 2);
            s += __shfl_xor_sync(0xffffffffu, s, 1);

            float mn   = fmaxf(m, s);
            float corr = __expf(m - mn);
            float p    = __expf(s - mn);
            l = l * corr + p;
            m = mn;
#pragma unroll
            for (int j = 0; j < 4; j++)
                acc[j] = acc[j] * corr + p * Vs[kk][lane + 32 * j];
        }
    }

    float inv = 1.0f / l;
    int b = bh >> 4, h = bh & 15;
    float* yo = g_y + ((size_t)(b * SEQ + qi)) * CDIM + h * HD;
#pragma unroll
    for (int j = 0; j < 4; j++)
        yo[lane + 32 * j] = acc[j] * inv;
}

// ---------------------------------------------------------------------------
extern "C" void kernel_launch(void* const* d_in, const int* in_sizes, int n_in,
                              void* d_out, int out_size)
{
    (void)in_sizes; (void)n_in; (void)out_size;
    const float* x    = (const float*)d_in[0];   // [8,512,2048]
    const float* Wqkv = (const float*)d_in[1];   // [6144,2048]
    const float* Wout = (const float*)d_in[2];   // [2048,2048]
    float* out = (float*)d_out;                  // [8,512,2048]

    float *qkv_p, *y_p;
    cudaGetSymbolAddress((void**)&qkv_p, g_qkv);
    cudaGetSymbolAddress((void**)&y_p, g_y);

    // 1) qkv = x @ Wqkv^T       (M=4096, N=6144, K=2048)
    sgemm_nt<<<dim3(F3 / 128, MTOK / 128), 256>>>(x, Wqkv, qkv_p, F3, CDIM);

    // 2) RoPE + split to [B,H,T,hd]
    rope_split_kernel<<<MTOK * NH, 128>>>();

    // 3) causal attention -> y [B,T,C]
    attn_kernel<<<dim3(SEQ / 8, BATCH * NH), 256>>>();

    // 4) out = y @ Wout^T       (M=4096, N=2048, K=2048)
    sgemm_nt<<<dim3(CDIM / 128, MTOK / 128), 256>>>(y_p, Wout, out, CDIM, CDIM);
}

// round 3
// speedup vs baseline: 2.4593x; 2.4593x over previous
#include <cuda_runtime.h>
#include <math.h>

#define BATCH 8
#define SEQ   512
#define CDIM  2048
#define NH    16
#define HD    128
#define MTOK  (BATCH*SEQ)      // 4096
#define F3    (3*CDIM)         // 6144

// Scratch (static device arrays; no allocation anywhere)
__device__ float g_qkv[MTOK * F3];
__device__ float g_q[BATCH*NH*SEQ*HD];
__device__ float g_k[BATCH*NH*SEQ*HD];
__device__ float g_v[BATCH*NH*SEQ*HD];
__device__ float g_y[MTOK * CDIM];
__device__ float g_xr[MTOK * CDIM];      // tf32-rounded x
__device__ float g_w1[F3 * CDIM];        // tf32-rounded Wqkv
__device__ float g_w2[CDIM * CDIM];      // tf32-rounded Wout

// ---------------------------------------------------------------------------
__device__ __forceinline__ unsigned smem_u32(const void* p) {
    unsigned a;
    asm("{ .reg .u64 t; cvta.to.shared.u64 t, %1; cvt.u32.u64 %0, t; }"
        : "=r"(a) : "l"(p));
    return a;
}
__device__ __forceinline__ unsigned tf32r(unsigned x) {
    unsigned r;
    asm("cvt.rna.tf32.f32 %0, %1;" : "=r"(r) : "r"(x));
    return r;
}
__device__ __forceinline__ void cp16(unsigned saddr, const void* gaddr) {
    asm volatile("cp.async.cg.shared.global [%0], [%1], 16;"
                 :: "r"(saddr), "l"(gaddr));
}

// tf32-round a float buffer (float4 grid-stride)
__global__ __launch_bounds__(256) void round_tf32_kernel(
    const float4* __restrict__ src, float4* __restrict__ dst, int n4)
{
    for (int i = blockIdx.x * blockDim.x + threadIdx.x; i < n4;
         i += gridDim.x * blockDim.x) {
        float4 v = src[i];
        uint4 u = *(uint4*)&v;
        u.x = tf32r(u.x); u.y = tf32r(u.y); u.z = tf32r(u.z); u.w = tf32r(u.w);
        dst[i] = *(float4*)&u;
    }
}

// ===========================================================================
// Tensor-core tf32 GEMM via mma.sync (arch-portable, runs on Blackwell HMMA):
//   C[M,N] = A[M,K] * B[N,K]^T   (row-major, K contiguous)
// 128x128x32 CTA tile, 256 threads = 8 warps (2x4), warp tile 64x32.
// cp.async double buffering; SMEM rows padded to 36 floats (conflict-free
// ldmatrix phases). Inputs must be pre-rounded to tf32.
// ===========================================================================
#define BM 128
#define BN 128
#define BK 32
#define LDK 36
#define TILE_B (BM * LDK * 4)              // 18432 bytes per matrix buffer
#define GEMM_SMEM (4 * TILE_B)             // A0 A1 B0 B1

__global__ __launch_bounds__(256, 2) void gemm_tf32mma(
    const float* __restrict__ A, const float* __restrict__ B,
    float* __restrict__ C, int Nd, int Kd)
{
    extern __shared__ char smem[];
    const unsigned sbase = smem_u32(smem);
    const int tid  = threadIdx.x;
    const int lane = tid & 31;
    const int wid  = tid >> 5;
    const int warpM = wid >> 2;            // 0..1
    const int warpN = wid & 3;             // 0..3
    const int m0 = blockIdx.y * BM;
    const int n0 = blockIdx.x * BN;

    // smem offsets: A buf b at b*TILE_B ; B buf b at 2*TILE_B + b*TILE_B
    const unsigned sA[2] = { sbase, sbase + TILE_B };
    const unsigned sB[2] = { sbase + 2 * TILE_B, sbase + 3 * TILE_B };

    // cp.async mapping: 1024 16B-chunks per matrix, 4 per thread
    const int row_ld  = tid >> 3;          // base row set: tid/8 + i*32
    const int col16   = tid & 7;           // 16B chunk within 32-float row

    float acc[4][4][4];
#pragma unroll
    for (int a = 0; a < 4; a++)
#pragma unroll
        for (int b = 0; b < 4; b++)
#pragma unroll
            for (int c = 0; c < 4; c++) acc[a][b][c] = 0.0f;

    const int KT = Kd / BK;

    // ---- prologue: load tile 0
    {
        const float* Ab = A + (size_t)m0 * Kd;
        const float* Bb = B + (size_t)n0 * Kd;
#pragma unroll
        for (int i = 0; i < 4; i++) {
            int r = row_ld + i * 32;
            cp16(sA[0] + (unsigned)(r * (LDK * 4) + col16 * 16),
                 Ab + (size_t)r * Kd + col16 * 4);
            cp16(sB[0] + (unsigned)(r * (LDK * 4) + col16 * 16),
                 Bb + (size_t)r * Kd + col16 * 4);
        }
        asm volatile("cp.async.commit_group;" ::: "memory");
    }

    for (int kt = 0; kt < KT; kt++) {
        const int cur = kt & 1;
        if (kt + 1 < KT) {
            const int nxt = cur ^ 1;
            const float* Ab = A + (size_t)m0 * Kd + (kt + 1) * BK;
            const float* Bb = B + (size_t)n0 * Kd + (kt + 1) * BK;
#pragma unroll
            for (int i = 0; i < 4; i++) {
                int r = row_ld + i * 32;
                cp16(sA[nxt] + (unsigned)(r * (LDK * 4) + col16 * 16),
                     Ab + (size_t)r * Kd + col16 * 4);
                cp16(sB[nxt] + (unsigned)(r * (LDK * 4) + col16 * 16),
                     Bb + (size_t)r * Kd + col16 * 4);
            }
            asm volatile("cp.async.commit_group;" ::: "memory");
            asm volatile("cp.async.wait_group 1;" ::: "memory");
        } else {
            asm volatile("cp.async.wait_group 0;" ::: "memory");
        }
        __syncthreads();

        // A ldmatrix base: row = warpM*64 + mt*16 + (lane&15), col = kk*8 + (lane>>4)*4
        const unsigned aRow = (unsigned)(warpM * 64 + (lane & 15));
        const unsigned aColHalf = (unsigned)((lane >> 4) * 4);
        // B ldmatrix base (x2): row = warpN*32 + nt*8 + (lane&7), col = kk*8 + ((lane&8)?4:0)
        const unsigned bRow = (unsigned)(warpN * 32 + (lane & 7));
        const unsigned bColHalf = (unsigned)((lane & 8) ? 4 : 0);

#pragma unroll
        for (int kk = 0; kk < 4; kk++) {
            unsigned af[4][4];
#pragma unroll
            for (int mt = 0; mt < 4; mt++) {
                unsigned addr = sA[cur]
                    + (aRow + mt * 16) * (LDK * 4)
                    + (kk * 8 + aColHalf) * 4;
                asm volatile(
                    "ldmatrix.sync.aligned.m8n8.x4.shared.b16 {%0,%1,%2,%3}, [%4];"
                    : "=r"(af[mt][0]), "=r"(af[mt][1]),
                      "=r"(af[mt][2]), "=r"(af[mt][3])
                    : "r"(addr));
            }
            unsigned bf[4][2];
#pragma unroll
            for (int nt = 0; nt < 4; nt++) {
                unsigned addr = sB[cur]
                    + (bRow + nt * 8) * (LDK * 4)
                    + (kk * 8 + bColHalf) * 4;
                asm volatile(
                    "ldmatrix.sync.aligned.m8n8.x2.shared.b16 {%0,%1}, [%2];"
                    : "=r"(bf[nt][0]), "=r"(bf[nt][1])
                    : "r"(addr));
            }
#pragma unroll
            for (int mt = 0; mt < 4; mt++)
#pragma unroll
                for (int nt = 0; nt < 4; nt++) {
                    asm volatile(
                        "mma.sync.aligned.m16n8k8.row.col.f32.tf32.tf32.f32 "
                        "{%0,%1,%2,%3}, {%4,%5,%6,%7}, {%8,%9}, {%0,%1,%2,%3};"
                        : "+f"(acc[mt][nt][0]), "+f"(acc[mt][nt][1]),
                          "+f"(acc[mt][nt][2]), "+f"(acc[mt][nt][3])
                        : "r"(af[mt][0]), "r"(af[mt][1]),
                          "r"(af[mt][2]), "r"(af[mt][3]),
                          "r"(bf[nt][0]), "r"(bf[nt][1]));
                }
        }
        __syncthreads();
    }

    // Epilogue: direct float2 stores
    const int rBase = m0 + warpM * 64 + (lane >> 2);
    const int cBase = n0 + warpN * 32 + (lane & 3) * 2;
#pragma unroll
    for (int mt = 0; mt < 4; mt++)
#pragma unroll
        for (int nt = 0; nt < 4; nt++) {
            float* p0 = C + (size_t)(rBase + mt * 16) * Nd + cBase + nt * 8;
            float* p1 = C + (size_t)(rBase + mt * 16 + 8) * Nd + cBase + nt * 8;
            *(float2*)p0 = make_float2(acc[mt][nt][0], acc[mt][nt][1]);
            *(float2*)p1 = make_float2(acc[mt][nt][2], acc[mt][nt][3]);
        }
}

// ---------------------------------------------------------------------------
// RoPE + split qkv -> q,k,v in [B,H,T,hd]
// ---------------------------------------------------------------------------
__global__ __launch_bounds__(128) void rope_split_kernel()
{
    int blk = blockIdx.x;
    int h  = blk % NH;
    int bt = blk / NH;
    int t  = bt % SEQ;
    int b  = bt / SEQ;
    int d  = threadIdx.x;

    const float* src = g_qkv + (size_t)bt * F3 + h * HD;
    size_t dst = ((size_t)(b * NH + h) * SEQ + t) * HD + d;

    float qv = src[d];
    float kv = src[CDIM + d];
    float vv = src[2 * CDIM + d];

    if (d < 16) {
        int i = d & 7;
        float freq = powf(10000.0f, -(float)i * 0.125f);
        float ang = (float)t * freq;
        float s, c;
        sincosf(ang, &s, &c);
        if (d < 8) {
            float q2 = src[d + 8];
            float k2 = src[CDIM + d + 8];
            qv = qv * c - q2 * s;
            kv = kv * c - k2 * s;
        } else {
            float q1 = src[d - 8];
            float k1 = src[CDIM + d - 8];
            qv = qv * c + q1 * s;
            kv = kv * c + k1 * s;
        }
    }
    g_q[dst] = qv;
    g_k[dst] = kv;
    g_v[dst] = vv;
}

// ---------------------------------------------------------------------------
// Causal attention, online softmax; writes tf32-rounded y (feeds out-GEMM).
// ---------------------------------------------------------------------------
#define KTT 32
__global__ __launch_bounds__(256) void attn_kernel()
{
    __shared__ float Ks[KTT][HD];
    __shared__ float Vs[KTT][HD];

    const int bh   = blockIdx.y;
    const int qt   = blockIdx.x;
    const int warp = threadIdx.x >> 5;
    const int lane = threadIdx.x & 31;
    const int qi   = qt * 8 + warp;

    const float* qrow = g_q + ((size_t)bh * SEQ + qi) * HD;
    float qr[4];
#pragma unroll
    for (int j = 0; j < 4; j++)
        qr[j] = qrow[lane + 32 * j] * 0.08838834764831845f;

    float m = -1e30f, l = 0.0f;
    float acc[4] = {0.f, 0.f, 0.f, 0.f};

    const int kmax = qt * 8 + 7;
    for (int kt0 = 0; kt0 <= kmax; kt0 += KTT) {
        __syncthreads();
        const float4* kb = (const float4*)(g_k + ((size_t)bh * SEQ + kt0) * HD);
        const float4* vb = (const float4*)(g_v + ((size_t)bh * SEQ + kt0) * HD);
        float4* ks4 = (float4*)Ks;
        float4* vs4 = (float4*)Vs;
#pragma unroll
        for (int i = threadIdx.x; i < KTT * HD / 4; i += 256) {
            ks4[i] = kb[i];
            vs4[i] = vb[i];
        }
        __syncthreads();

        int kend = qi - kt0 + 1;
        if (kend > KTT) kend = KTT;
        for (int kk = 0; kk < kend; kk++) {
            float s = qr[0] * Ks[kk][lane]      + qr[1] * Ks[kk][lane + 32]
                    + qr[2] * Ks[kk][lane + 64] + qr[3] * Ks[kk][lane + 96];
            s += __shfl_xor_sync(0xffffffffu, s, 16);
            s += __shfl_xor_sync(0xffffffffu, s, 8);
            s += __shfl_xor_sync(0xffffffffu, s, 4);
            s += __shfl_xor_sync(0xffffffffu, s, 2);
            s += __shfl_xor_sync(0xffffffffu, s, 1);

            float mn   = fmaxf(m, s);
            float corr = __expf(m - mn);
            float p    = __expf(s - mn);
            l = l * corr + p;
            m = mn;
#pragma unroll
            for (int j = 0; j < 4; j++)
                acc[j] = acc[j] * corr + p * Vs[kk][lane + 32 * j];
        }
    }

    float inv = 1.0f / l;
    int b = bh >> 4, h = bh & 15;
    float* yo = g_y + ((size_t)(b * SEQ + qi)) * CDIM + h * HD;
#pragma unroll
    for (int j = 0; j < 4; j++) {
        float v = acc[j] * inv;
        yo[lane + 32 * j] = __uint_as_float(tf32r(__float_as_uint(v)));
    }
}

// ---------------------------------------------------------------------------
extern "C" void kernel_launch(void* const* d_in, const int* in_sizes, int n_in,
                              void* d_out, int out_size)
{
    (void)in_sizes; (void)n_in; (void)out_size;
    const float* x    = (const float*)d_in[0];
    const float* Wqkv = (const float*)d_in[1];
    const float* Wout = (const float*)d_in[2];
    float* out = (float*)d_out;

    float *qkv_p, *y_p, *xr_p, *w1_p, *w2_p;
    cudaGetSymbolAddress((void**)&qkv_p, g_qkv);
    cudaGetSymbolAddress((void**)&y_p,  g_y);
    cudaGetSymbolAddress((void**)&xr_p, g_xr);
    cudaGetSymbolAddress((void**)&w1_p, g_w1);
    cudaGetSymbolAddress((void**)&w2_p, g_w2);

    cudaFuncSetAttribute(gemm_tf32mma,
                         cudaFuncAttributeMaxDynamicSharedMemorySize, GEMM_SMEM);

    // 0) tf32-round GEMM inputs (removes mma truncation bias)
    round_tf32_kernel<<<2048, 256>>>((const float4*)x,    (float4*)xr_p, MTOK * CDIM / 4);
    round_tf32_kernel<<<2048, 256>>>((const float4*)Wqkv, (float4*)w1_p, F3 * CDIM / 4);
    round_tf32_kernel<<<2048, 256>>>((const float4*)Wout, (float4*)w2_p, CDIM * CDIM / 4);

    // 1) qkv = x @ Wqkv^T
    gemm_tf32mma<<<dim3(F3 / BN, MTOK / BM), 256, GEMM_SMEM>>>(xr_p, w1_p, qkv_p, F3, CDIM);

    // 2) RoPE + split
    rope_split_kernel<<<MTOK * NH, 128>>>();

    // 3) causal attention -> y (tf32-rounded)
    attn_kernel<<<dim3(SEQ / 8, BATCH * NH), 256>>>();

    // 4) out = y @ Wout^T
    gemm_tf32mma<<<dim3(CDIM / BN, MTOK / BM), 256, GEMM_SMEM>>>(y_p, w2_p, out, CDIM, CDIM);
}

// round 5
// speedup vs baseline: 4.2640x; 1.7338x over previous
#include <cuda_runtime.h>
#include <math.h>

#define BATCH 8
#define SEQ   512
#define CDIM  2048
#define NH    16
#define HD    128
#define MTOK  (BATCH*SEQ)      // 4096
#define F3    (3*CDIM)         // 6144

// Scratch (static device arrays; no allocation anywhere)
__device__ float g_qkv[MTOK * F3];
__device__ float g_q [BATCH*NH*SEQ*HD];   // [bh][t][d] scaled+tf32-rounded
__device__ float g_k [BATCH*NH*SEQ*HD];   // [bh][t][d] tf32-rounded
__device__ float g_vT[BATCH*NH*HD*SEQ];   // [bh][d][t] tf32-rounded (transposed)
__device__ float g_y [MTOK * CDIM];       // [b,t,C] tf32-rounded
__device__ float g_xr[MTOK * CDIM];
__device__ float g_w1[F3 * CDIM];
__device__ float g_w2[CDIM * CDIM];

// ---------------------------------------------------------------------------
__device__ __forceinline__ unsigned smem_u32(const void* p) {
    unsigned a;
    asm("{ .reg .u64 t; cvta.to.shared.u64 t, %1; cvt.u32.u64 %0, t; }"
        : "=r"(a) : "l"(p));
    return a;
}
__device__ __forceinline__ unsigned tf32r(unsigned x) {
    unsigned r;
    asm("cvt.rna.tf32.f32 %0, %1;" : "=r"(r) : "r"(x));
    return r;
}
__device__ __forceinline__ float tf32f(float x) {
    return __uint_as_float(tf32r(__float_as_uint(x)));
}
__device__ __forceinline__ void cp16(unsigned saddr, const void* gaddr) {
    asm volatile("cp.async.cg.shared.global [%0], [%1], 16;"
                 :: "r"(saddr), "l"(gaddr));
}
__device__ __forceinline__ void ldsm_x4(unsigned addr, unsigned& r0, unsigned& r1,
                                        unsigned& r2, unsigned& r3) {
    asm volatile("ldmatrix.sync.aligned.m8n8.x4.shared.b16 {%0,%1,%2,%3}, [%4];"
                 : "=r"(r0), "=r"(r1), "=r"(r2), "=r"(r3) : "r"(addr));
}
__device__ __forceinline__ void mma_tf32(float* c, const unsigned* a,
                                         unsigned b0, unsigned b1) {
    asm volatile(
        "mma.sync.aligned.m16n8k8.row.col.f32.tf32.tf32.f32 "
        "{%0,%1,%2,%3}, {%4,%5,%6,%7}, {%8,%9}, {%0,%1,%2,%3};"
        : "+f"(c[0]), "+f"(c[1]), "+f"(c[2]), "+f"(c[3])
        : "r"(a[0]), "r"(a[1]), "r"(a[2]), "r"(a[3]), "r"(b0), "r"(b1));
}

// tf32-round a float buffer (float4 grid-stride)
__global__ __launch_bounds__(256) void round_tf32_kernel(
    const float4* __restrict__ src, float4* __restrict__ dst, int n4)
{
    for (int i = blockIdx.x * blockDim.x + threadIdx.x; i < n4;
         i += gridDim.x * blockDim.x) {
        float4 v = src[i];
        uint4 u = *(uint4*)&v;
        u.x = tf32r(u.x); u.y = tf32r(u.y); u.z = tf32r(u.z); u.w = tf32r(u.w);
        dst[i] = *(float4*)&u;
    }
}

// ===========================================================================
// tf32 mma.sync GEMM: C[M,N] = A[M,K]*B[N,K]^T, 128x128x32 tile, 256 thr,
// 3-stage cp.async pipeline, ONE barrier per K-iteration.
// ===========================================================================
#define BM 128
#define BN 128
#define BK 32
#define LDK 36
#define TILE_B (BM * LDK * 4)               // 18432 B per matrix per stage
#define STAGE_B (2 * TILE_B)                // A+B per stage
#define GEMM_SMEM (3 * STAGE_B)             // 110592 B

__global__ __launch_bounds__(256, 2) void gemm_tf32mma(
    const float* __restrict__ A, const float* __restrict__ B,
    float* __restrict__ C, int Nd, int Kd)
{
    extern __shared__ char smem[];
    const unsigned sbase = smem_u32(smem);
    const int tid  = threadIdx.x;
    const int lane = tid & 31;
    const int wid  = tid >> 5;
    const int warpM = wid >> 2;
    const int warpN = wid & 3;
    const int m0 = blockIdx.y * BM;
    const int n0 = blockIdx.x * BN;

    const int row_ld = tid >> 3;
    const int col16  = tid & 7;

    float acc[4][4][4];
#pragma unroll
    for (int a = 0; a < 4; a++)
#pragma unroll
        for (int b = 0; b < 4; b++)
#pragma unroll
            for (int c = 0; c < 4; c++) acc[a][b][c] = 0.0f;

    const int KT = Kd / BK;

    // prologue: stages 0,1
#pragma unroll
    for (int pk = 0; pk < 2; pk++) {
        const float* Ab = A + (size_t)m0 * Kd + pk * BK;
        const float* Bb = B + (size_t)n0 * Kd + pk * BK;
        unsigned sA = sbase + pk * STAGE_B;
        unsigned sB = sA + TILE_B;
#pragma unroll
        for (int i = 0; i < 4; i++) {
            int r = row_ld + i * 32;
            cp16(sA + (unsigned)(r * (LDK * 4) + col16 * 16),
                 Ab + (size_t)r * Kd + col16 * 4);
            cp16(sB + (unsigned)(r * (LDK * 4) + col16 * 16),
                 Bb + (size_t)r * Kd + col16 * 4);
        }
        asm volatile("cp.async.commit_group;" ::: "memory");
    }

    const unsigned aRow = (unsigned)(warpM * 64 + (lane & 15));
    const unsigned aHalf = (unsigned)((lane >> 4) * 16);
    const unsigned bRow = (unsigned)(warpN * 32 + (lane & 15));

    for (int kt = 0; kt < KT; kt++) {
        if (kt < KT - 1)
            asm volatile("cp.async.wait_group 1;" ::: "memory");
        else
            asm volatile("cp.async.wait_group 0;" ::: "memory");
        __syncthreads();

        if (kt + 2 < KT) {
            int st = (kt + 2) % 3;
            const float* Ab = A + (size_t)m0 * Kd + (kt + 2) * BK;
            const float* Bb = B + (size_t)n0 * Kd + (kt + 2) * BK;
            unsigned sA = sbase + st * STAGE_B;
            unsigned sB = sA + TILE_B;
#pragma unroll
            for (int i = 0; i < 4; i++) {
                int r = row_ld + i * 32;
                cp16(sA + (unsigned)(r * (LDK * 4) + col16 * 16),
                     Ab + (size_t)r * Kd + col16 * 4);
                cp16(sB + (unsigned)(r * (LDK * 4) + col16 * 16),
                     Bb + (size_t)r * Kd + col16 * 4);
            }
            asm volatile("cp.async.commit_group;" ::: "memory");
        }

        const unsigned sAc = sbase + (kt % 3) * STAGE_B;
        const unsigned sBc = sAc + TILE_B;

#pragma unroll
        for (int kk = 0; kk < 4; kk++) {
            unsigned af[4][4];
#pragma unroll
            for (int mt = 0; mt < 4; mt++)
                ldsm_x4(sAc + (aRow + mt * 16) * (LDK * 4) + kk * 32 + aHalf,
                        af[mt][0], af[mt][1], af[mt][2], af[mt][3]);
            unsigned bf[4][2];
#pragma unroll
            for (int ntp = 0; ntp < 2; ntp++) {
                unsigned r0, r1, r2, r3;
                ldsm_x4(sBc + (bRow + ntp * 16) * (LDK * 4) + kk * 32 + aHalf,
                        r0, r1, r2, r3);
                bf[2 * ntp][0] = r0;     bf[2 * ntp][1] = r2;
                bf[2 * ntp + 1][0] = r1; bf[2 * ntp + 1][1] = r3;
            }
#pragma unroll
            for (int mt = 0; mt < 4; mt++)
#pragma unroll
                for (int nt = 0; nt < 4; nt++)
                    mma_tf32(acc[mt][nt], af[mt], bf[nt][0], bf[nt][1]);
        }
    }

    const int rBase = m0 + warpM * 64 + (lane >> 2);
    const int cBase = n0 + warpN * 32 + (lane & 3) * 2;
#pragma unroll
    for (int mt = 0; mt < 4; mt++)
#pragma unroll
        for (int nt = 0; nt < 4; nt++) {
            float* p0 = C + (size_t)(rBase + mt * 16) * Nd + cBase + nt * 8;
            float* p1 = C + (size_t)(rBase + mt * 16 + 8) * Nd + cBase + nt * 8;
            *(float2*)p0 = make_float2(acc[mt][nt][0], acc[mt][nt][1]);
            *(float2*)p1 = make_float2(acc[mt][nt][2], acc[mt][nt][3]);
        }
}

// ---------------------------------------------------------------------------
// RoPE + split. Writes q (scaled, tf32), k (tf32) in [bh][t][d], and
// v TRANSPOSED (tf32) in [bh][d][t] via smem transpose.
// grid (SEQ/32, BATCH*NH), 128 threads.
// ---------------------------------------------------------------------------
__global__ __launch_bounds__(128) void rope_kernel()
{
    __shared__ float vsm[128][33];
    const int bh = blockIdx.y;
    const int b = bh >> 4, h = bh & 15;
    const int t0 = blockIdx.x * 32;
    const int d = threadIdx.x;

    float freq = 0.0f;
    if (d < 16) freq = __powf(10000.0f, -(float)(d & 7) * 0.125f);

    for (int tl = 0; tl < 32; tl++) {
        int t = t0 + tl;
        const float* src = g_qkv + (size_t)(b * SEQ + t) * F3 + h * HD;
        float qv = src[d];
        float kv = src[CDIM + d];
        float vv = src[2 * CDIM + d];
        if (d < 16) {
            float s, c;
            __sincosf((float)t * freq, &s, &c);
            if (d < 8) {
                qv = qv * c - src[d + 8] * s;
                kv = kv * c - src[CDIM + d + 8] * s;
            } else {
                qv = qv * c + src[d - 8] * s;
                kv = kv * c + src[CDIM + d - 8] * s;
            }
        }
        size_t dst = ((size_t)bh * SEQ + t) * HD + d;
        g_q[dst] = tf32f(qv * 0.08838834764831845f);
        g_k[dst] = tf32f(kv);
        vsm[d][tl] = tf32f(vv);
    }
    __syncthreads();
#pragma unroll
    for (int i = 0; i < 8; i++) {                 // 8 iters x 16 rows = 128 rows
        int row = (threadIdx.x >> 3) + i * 16;
        int c = (threadIdx.x & 7) * 4;
        float4 v = make_float4(vsm[row][c], vsm[row][c + 1],
                               vsm[row][c + 2], vsm[row][c + 3]);
        *(float4*)(g_vT + ((size_t)bh * HD + row) * SEQ + t0 + c) = v;
    }
}

// ===========================================================================
// Flash attention with tf32 mma: CTA = 64 queries x 1 (b,h), Bc=32 keys.
// 4 warps; warp = 16 query rows. S = Q K^T (mma), online softmax on frags,
// P via smem -> mma with V^T. cp.async 1-deep K/V prefetch.
// ===========================================================================
#define AK_PITCH 528                         // 132 floats
#define AV_PITCH 144                         // 36 floats
#define OFF_K0   0
#define OFF_K1   16896
#define OFF_V0   33792
#define OFF_V1   52224
#define OFF_P    70656
#define ATTN_SMEM 79872

__global__ __launch_bounds__(128, 2) void fattn_kernel()
{
    extern __shared__ char smem[];
    const unsigned sb = smem_u32(smem);
    const int bh = blockIdx.y;
    const int qt = blockIdx.x;
    const int q0 = qt * 64;
    const int jmax = 2 * qt + 1;
    const int tid = threadIdx.x;
    const int lane = tid & 31;
    const int wq = tid >> 5;

    // ---- stage Q tile (64 x 128) through smem, grab A-fragments
    {
        const float* qg = g_q + ((size_t)bh * SEQ + q0) * HD;
#pragma unroll
        for (int i = 0; i < 16; i++) {
            int id = tid + i * 128;
            int row = id >> 5, c16 = id & 31;
            cp16(sb + row * AK_PITCH + c16 * 16, qg + row * HD + c16 * 4);
        }
        asm volatile("cp.async.commit_group;" ::: "memory");
        asm volatile("cp.async.wait_group 0;" ::: "memory");
        __syncthreads();
    }
    unsigned qf[16][4];
    {
        unsigned qaddr = sb + (wq * 16 + (lane & 15)) * AK_PITCH + (lane >> 4) * 16;
#pragma unroll
        for (int kk = 0; kk < 16; kk++)
            ldsm_x4(qaddr + kk * 32, qf[kk][0], qf[kk][1], qf[kk][2], qf[kk][3]);
    }
    __syncthreads();

    float m1 = -1e30f, m2 = -1e30f, l1 = 0.0f, l2 = 0.0f;
    float oacc[16][4];
#pragma unroll
    for (int nt = 0; nt < 16; nt++)
#pragma unroll
        for (int c = 0; c < 4; c++) oacc[nt][c] = 0.0f;

    // tile loader (K [32,128] + V^T [128,32])
    auto load_tile = [&](int j) {
        unsigned kb = sb + ((j & 1) ? OFF_K1 : OFF_K0);
        unsigned vb = sb + ((j & 1) ? OFF_V1 : OFF_V0);
        const float* kg = g_k + ((size_t)bh * SEQ + j * 32) * HD;
        const float* vg = g_vT + (size_t)bh * HD * SEQ + j * 32;
#pragma unroll
        for (int i = 0; i < 8; i++) {
            int id = tid + i * 128;
            int kr = id >> 5, kc = id & 31;
            cp16(kb + kr * AK_PITCH + kc * 16, kg + kr * HD + kc * 4);
            int vr = id >> 3, vc = id & 7;
            cp16(vb + vr * AV_PITCH + vc * 16, vg + (size_t)vr * SEQ + vc * 4);
        }
        asm volatile("cp.async.commit_group;" ::: "memory");
    };

    load_tile(0);

    const int rowg1 = q0 + wq * 16 + (lane >> 2);

    for (int j = 0; j <= jmax; j++) {
        asm volatile("cp.async.wait_group 0;" ::: "memory");
        __syncthreads();
        if (j < jmax) load_tile(j + 1);

        // ---- S = Q K^T  (warp: 16 rows x 32 keys)
        float sacc[4][4];
#pragma unroll
        for (int nt = 0; nt < 4; nt++)
#pragma unroll
            for (int c = 0; c < 4; c++) sacc[nt][c] = 0.0f;

        const unsigned kbase = sb + ((j & 1) ? OFF_K1 : OFF_K0);
        const unsigned half16 = (unsigned)((lane >> 4) * 16);
#pragma unroll
        for (int kk = 0; kk < 16; kk++) {
            unsigned bf[4][2];
#pragma unroll
            for (int ntp = 0; ntp < 2; ntp++) {
                unsigned r0, r1, r2, r3;
                ldsm_x4(kbase + (ntp * 16 + (lane & 15)) * AK_PITCH + kk * 32 + half16,
                        r0, r1, r2, r3);
                bf[2 * ntp][0] = r0;     bf[2 * ntp][1] = r2;
                bf[2 * ntp + 1][0] = r1; bf[2 * ntp + 1][1] = r3;
            }
#pragma unroll
            for (int nt = 0; nt < 4; nt++)
                mma_tf32(sacc[nt], qf[kk], bf[nt][0], bf[nt][1]);
        }

        // ---- causal mask
        if (j * 32 + 31 > q0 + wq * 16) {
#pragma unroll
            for (int nt = 0; nt < 4; nt++) {
                int colb = j * 32 + nt * 8 + (lane & 3) * 2;
                if (colb     > rowg1)     sacc[nt][0] = -1e30f;
                if (colb + 1 > rowg1)     sacc[nt][1] = -1e30f;
                if (colb     > rowg1 + 8) sacc[nt][2] = -1e30f;
                if (colb + 1 > rowg1 + 8) sacc[nt][3] = -1e30f;
            }
        }

        // ---- online softmax (rows r1 = lane>>2, r2 = r1+8)
        float tm1 = -1e30f, tm2 = -1e30f;
#pragma unroll
        for (int nt = 0; nt < 4; nt++) {
            tm1 = fmaxf(tm1, fmaxf(sacc[nt][0], sacc[nt][1]));
            tm2 = fmaxf(tm2, fmaxf(sacc[nt][2], sacc[nt][3]));
        }
        tm1 = fmaxf(tm1, __shfl_xor_sync(0xffffffffu, tm1, 1));
        tm1 = fmaxf(tm1, __shfl_xor_sync(0xffffffffu, tm1, 2));
        tm2 = fmaxf(tm2, __shfl_xor_sync(0xffffffffu, tm2, 1));
        tm2 = fmaxf(tm2, __shfl_xor_sync(0xffffffffu, tm2, 2));

        float m1n = fmaxf(m1, tm1), m2n = fmaxf(m2, tm2);
        float corr1 = __expf(m1 - m1n), corr2 = __expf(m2 - m2n);
        m1 = m1n; m2 = m2n;

        float rs1 = 0.0f, rs2 = 0.0f;
#pragma unroll
        for (int nt = 0; nt < 4; nt++) {
            sacc[nt][0] = __expf(sacc[nt][0] - m1n);
            sacc[nt][1] = __expf(sacc[nt][1] - m1n);
            sacc[nt][2] = __expf(sacc[nt][2] - m2n);
            sacc[nt][3] = __expf(sacc[nt][3] - m2n);
            rs1 += sacc[nt][0] + sacc[nt][1];
            rs2 += sacc[nt][2] + sacc[nt][3];
        }
        rs1 += __shfl_xor_sync(0xffffffffu, rs1, 1);
        rs1 += __shfl_xor_sync(0xffffffffu, rs1, 2);
        rs2 += __shfl_xor_sync(0xffffffffu, rs2, 1);
        rs2 += __shfl_xor_sync(0xffffffffu, rs2, 2);
        l1 = l1 * corr1 + rs1;
        l2 = l2 * corr2 + rs2;

#pragma unroll
        for (int nt = 0; nt < 16; nt++) {
            oacc[nt][0] *= corr1; oacc[nt][1] *= corr1;
            oacc[nt][2] *= corr2; oacc[nt][3] *= corr2;
        }

        // ---- P -> smem (tf32-rounded)
        {
            int pr1 = wq * 16 + (lane >> 2);
            int pc = (lane & 3) * 2;
#pragma unroll
            for (int nt = 0; nt < 4; nt++) {
                *(float2*)(smem + OFF_P + (pr1 * 36 + nt * 8 + pc) * 4) =
                    make_float2(tf32f(sacc[nt][0]), tf32f(sacc[nt][1]));
                *(float2*)(smem + OFF_P + ((pr1 + 8) * 36 + nt * 8 + pc) * 4) =
                    make_float2(tf32f(sacc[nt][2]), tf32f(sacc[nt][3]));
            }
        }
        __syncthreads();

        // ---- O += P V
        const unsigned vbase = sb + ((j & 1) ? OFF_V1 : OFF_V0);
        const unsigned paddr = sb + OFF_P + (wq * 16 + (lane & 15)) * AV_PITCH + half16;
#pragma unroll
        for (int kkc = 0; kkc < 4; kkc++) {
            unsigned pf[4];
            ldsm_x4(paddr + kkc * 32, pf[0], pf[1], pf[2], pf[3]);
#pragma unroll
            for (int ntp = 0; ntp < 8; ntp++) {
                unsigned r0, r1, r2, r3;
                ldsm_x4(vbase + (ntp * 16 + (lane & 15)) * AV_PITCH + kkc * 32 + half16,
                        r0, r1, r2, r3);
                mma_tf32(oacc[2 * ntp],     pf, r0, r2);
                mma_tf32(oacc[2 * ntp + 1], pf, r1, r3);
            }
        }
        __syncthreads();
    }

    // ---- epilogue: y = O / l, tf32-rounded, to [b,t,C]
    float inv1 = 1.0f / l1, inv2 = 1.0f / l2;
    int b = bh >> 4, h = bh & 15;
    int row1 = q0 + wq * 16 + (lane >> 2);
#pragma unroll
    for (int nt = 0; nt < 16; nt++) {
        int d = nt * 8 + (lane & 3) * 2;
        float* p0 = g_y + (size_t)(b * SEQ + row1) * CDIM + h * HD + d;
        float* p1 = g_y + (size_t)(b * SEQ + row1 + 8) * CDIM + h * HD + d;
        *(float2*)p0 = make_float2(tf32f(oacc[nt][0] * inv1), tf32f(oacc[nt][1] * inv1));
        *(float2*)p1 = make_float2(tf32f(oacc[nt][2] * inv2), tf32f(oacc[nt][3] * inv2));
    }
}

// ---------------------------------------------------------------------------
extern "C" void kernel_launch(void* const* d_in, const int* in_sizes, int n_in,
                              void* d_out, int out_size)
{
    (void)in_sizes; (void)n_in; (void)out_size;
    const float* x    = (const float*)d_in[0];
    const float* Wqkv = (const float*)d_in[1];
    const float* Wout = (const float*)d_in[2];
    float* out = (float*)d_out;

    float *qkv_p, *y_p, *xr_p, *w1_p, *w2_p;
    cudaGetSymbolAddress((void**)&qkv_p, g_qkv);
    cudaGetSymbolAddress((void**)&y_p,  g_y);
    cudaGetSymbolAddress((void**)&xr_p, g_xr);
    cudaGetSymbolAddress((void**)&w1_p, g_w1);
    cudaGetSymbolAddress((void**)&w2_p, g_w2);

    cudaFuncSetAttribute(gemm_tf32mma,
                         cudaFuncAttributeMaxDynamicSharedMemorySize, GEMM_SMEM);
    cudaFuncSetAttribute(fattn_kernel,
                         cudaFuncAttributeMaxDynamicSharedMemorySize, ATTN_SMEM);

    // 0) tf32-round GEMM inputs
    round_tf32_kernel<<<1184, 256>>>((const float4*)x,    (float4*)xr_p, MTOK * CDIM / 4);
    round_tf32_kernel<<<1184, 256>>>((const float4*)Wqkv, (float4*)w1_p, F3 * CDIM / 4);
    round_tf32_kernel<<<1184, 256>>>((const float4*)Wout, (float4*)w2_p, CDIM * CDIM / 4);

    // 1) qkv = x @ Wqkv^T
    gemm_tf32mma<<<dim3(F3 / BN, MTOK / BM), 256, GEMM_SMEM>>>(xr_p, w1_p, qkv_p, F3, CDIM);

    // 2) RoPE + split + V transpose
    rope_kernel<<<dim3(SEQ / 32, BATCH * NH), 128>>>();

    // 3) flash attention (tf32 mma) -> y
    fattn_kernel<<<dim3(SEQ / 64, BATCH * NH), 128, ATTN_SMEM>>>();

    // 4) out = y @ Wout^T
    gemm_tf32mma<<<dim3(CDIM / BN, MTOK / BM), 256, GEMM_SMEM>>>(y_p, w2_p, out, CDIM, CDIM);
}